// round 1
// baseline (speedup 1.0000x reference)
#include <cuda_runtime.h>
#include <cuda_bf16.h>

#define N_NODES 50000
#define N_EDGES 600000
#define D 128
#define NT 16
#define CHUNK 1024
#define NCHUNK 49   // ceil(50000/1024)

// ---------------- scratch (static __device__, no allocs) ----------------
__device__ float g_x0[N_NODES * D];     // embedded node features
__device__ float g_h1[N_NODES * D];     // layer-1 output
__device__ float g_agg[N_NODES * D];    // mean-aggregated neighbor features
__device__ int   g_deg[NCHUNK * CHUNK]; // padded degree array
__device__ int   g_off[N_NODES];        // CSR row offsets (exclusive scan of deg)
__device__ int   g_cur[N_NODES];        // fill cursors
__device__ int   g_csr[N_EDGES];        // src lists grouped by dst
__device__ int   g_csum[NCHUNK];        // per-chunk sums -> offsets
__device__ float g_W2lc[D * NT];        // W2_l @ Wc (folded)
__device__ float g_W2rc[D * NT];        // W2_r @ Wc (folded)
__device__ float g_bcp[NT];             // b2 @ Wc + bc (folded)

// ---------------- CSR construction ----------------
__global__ void k_zero_deg() {
    int i = blockIdx.x * blockDim.x + threadIdx.x;
    if (i < NCHUNK * CHUNK) g_deg[i] = 0;
}

__global__ void k_count(const int* __restrict__ dst) {
    int e = blockIdx.x * blockDim.x + threadIdx.x;
    if (e < N_EDGES) atomicAdd(&g_deg[dst[e]], 1);
}

__global__ void k_chunksum() {
    __shared__ int s[256];
    int b = blockIdx.x, t = threadIdx.x;
    int base = b * CHUNK + t * 4;
    int v = g_deg[base] + g_deg[base + 1] + g_deg[base + 2] + g_deg[base + 3];
    s[t] = v;
    __syncthreads();
    for (int o = 128; o > 0; o >>= 1) {
        if (t < o) s[t] += s[t + o];
        __syncthreads();
    }
    if (t == 0) g_csum[b] = s[0];
}

__global__ void k_chunkoff() {
    if (threadIdx.x == 0) {
        int run = 0;
        for (int b = 0; b < NCHUNK; b++) { int v = g_csum[b]; g_csum[b] = run; run += v; }
    }
}

__global__ void k_scan() {
    __shared__ int s[CHUNK];
    int b = blockIdx.x, t = threadIdx.x;
    int g = b * CHUNK + t;
    int v = g_deg[g];
    s[t] = v;
    __syncthreads();
    for (int o = 1; o < CHUNK; o <<= 1) {
        int tmp = (t >= o) ? s[t - o] : 0;
        __syncthreads();
        s[t] += tmp;
        __syncthreads();
    }
    if (g < N_NODES) {
        int excl = g_csum[b] + s[t] - v;
        g_off[g] = excl;
        g_cur[g] = excl;
    }
}

__global__ void k_fill(const int* __restrict__ src, const int* __restrict__ dst) {
    int e = blockIdx.x * blockDim.x + threadIdx.x;
    if (e < N_EDGES) {
        int p = atomicAdd(&g_cur[dst[e]], 1);
        g_csr[p] = src[e];
    }
}

// ---------------- embedding gather: x0 = emb[entity] ----------------
__global__ void k_gather(const int* __restrict__ entity, const float* __restrict__ emb) {
    int warp = (blockIdx.x * blockDim.x + threadIdx.x) >> 5;
    int lane = threadIdx.x & 31;
    if (warp >= N_NODES) return;
    int e = entity[warp];
    const float4* s = (const float4*)(emb + (size_t)e * D);
    float4* d = (float4*)(g_x0 + (size_t)warp * D);
    d[lane] = s[lane];
}

// ---------------- fold layer-2 weights through classifier ----------------
__global__ void k_combine(const float* __restrict__ W2l, const float* __restrict__ W2r,
                          const float* __restrict__ b2,  const float* __restrict__ Wc,
                          const float* __restrict__ bc) {
    __shared__ float sWc[D * NT];
    for (int i = threadIdx.x; i < D * NT; i += blockDim.x) sWc[i] = Wc[i];
    __syncthreads();
    const float* W = (blockIdx.x == 0) ? W2l : W2r;
    float* out = (blockIdx.x == 0) ? g_W2lc : g_W2rc;
    for (int o = threadIdx.x; o < D * NT; o += blockDim.x) {
        int i = o >> 4, c = o & 15;
        float acc = 0.f;
        #pragma unroll 8
        for (int k = 0; k < D; k++) acc += W[i * D + k] * sWc[k * NT + c];
        out[o] = acc;
    }
    if (blockIdx.x == 0 && threadIdx.x < NT) {
        int c = threadIdx.x;
        float acc = bc[c];
        for (int k = 0; k < D; k++) acc += b2[k] * sWc[k * NT + c];
        g_bcp[c] = acc;
    }
}

// ---------------- mean aggregation: warp per node ----------------
__global__ __launch_bounds__(256) void k_agg(int useH1) {
    const float* __restrict__ X = useH1 ? g_h1 : g_x0;
    int warp = (blockIdx.x * blockDim.x + threadIdx.x) >> 5;
    int lane = threadIdx.x & 31;
    if (warp >= N_NODES) return;
    int start = g_off[warp];
    int d = g_deg[warp];
    float ax = 0.f, ay = 0.f, az = 0.f, aw = 0.f;
    int e = 0;
    for (; e + 4 <= d; e += 4) {
        int s0 = g_csr[start + e + 0];
        int s1 = g_csr[start + e + 1];
        int s2 = g_csr[start + e + 2];
        int s3 = g_csr[start + e + 3];
        float4 v0 = ((const float4*)(X + (size_t)s0 * D))[lane];
        float4 v1 = ((const float4*)(X + (size_t)s1 * D))[lane];
        float4 v2 = ((const float4*)(X + (size_t)s2 * D))[lane];
        float4 v3 = ((const float4*)(X + (size_t)s3 * D))[lane];
        ax += v0.x + v1.x + v2.x + v3.x;
        ay += v0.y + v1.y + v2.y + v3.y;
        az += v0.z + v1.z + v2.z + v3.z;
        aw += v0.w + v1.w + v2.w + v3.w;
    }
    for (; e < d; e++) {
        int s0 = g_csr[start + e];
        float4 v0 = ((const float4*)(X + (size_t)s0 * D))[lane];
        ax += v0.x; ay += v0.y; az += v0.z; aw += v0.w;
    }
    float inv = 1.0f / (float)max(d, 1);
    float4 r = make_float4(ax * inv, ay * inv, az * inv, aw * inv);
    ((float4*)(g_agg + (size_t)warp * D))[lane] = r;
}

// ---------------- layer-1 fused GEMM: h1 = relu(agg@W1l + x0@W1r + b1) ----
// 128x128 block tile, K=256 (8 chunks from agg/W1l, 8 from x0/W1r), 256 thr, 8x8/thread
__global__ __launch_bounds__(256) void k_gemm(const float* __restrict__ B1,
                                              const float* __restrict__ B2,
                                              const float* __restrict__ bias) {
    __shared__ float As[16][128];
    __shared__ float Bs[16][128];
    int bm = blockIdx.x * 128;
    int tid = threadIdx.x;
    int tx = tid & 15, ty = tid >> 4;
    float acc[8][8];
    #pragma unroll
    for (int i = 0; i < 8; i++)
        #pragma unroll
        for (int j = 0; j < 8; j++) acc[i][j] = 0.f;

    for (int ch = 0; ch < 16; ch++) {
        const float* A = (ch < 8) ? g_agg : g_x0;
        const float* B = (ch < 8) ? B1 : B2;
        int k0 = (ch & 7) * 16;
        #pragma unroll
        for (int l = 0; l < 2; l++) {
            int idx = tid * 2 + l;          // 0..511
            int r = idx >> 2, c4 = idx & 3; // 128 rows x 4 float4
            int row = bm + r;
            float4 v = make_float4(0.f, 0.f, 0.f, 0.f);
            if (row < N_NODES) v = *(const float4*)(A + (size_t)row * D + k0 + c4 * 4);
            As[c4 * 4 + 0][r] = v.x;
            As[c4 * 4 + 1][r] = v.y;
            As[c4 * 4 + 2][r] = v.z;
            As[c4 * 4 + 3][r] = v.w;
        }
        #pragma unroll
        for (int l = 0; l < 2; l++) {
            int idx = tid * 2 + l;
            int r = idx >> 5, c4 = idx & 31; // 16 rows x 32 float4
            *(float4*)&Bs[r][c4 * 4] = *(const float4*)(B + (size_t)(k0 + r) * D + c4 * 4);
        }
        __syncthreads();
        #pragma unroll
        for (int k = 0; k < 16; k++) {
            float a[8], b[8];
            *(float4*)&a[0] = *(const float4*)&As[k][ty * 8];
            *(float4*)&a[4] = *(const float4*)&As[k][ty * 8 + 4];
            *(float4*)&b[0] = *(const float4*)&Bs[k][tx * 8];
            *(float4*)&b[4] = *(const float4*)&Bs[k][tx * 8 + 4];
            #pragma unroll
            for (int i = 0; i < 8; i++)
                #pragma unroll
                for (int j = 0; j < 8; j++) acc[i][j] += a[i] * b[j];
        }
        __syncthreads();
    }

    float bb[8];
    #pragma unroll
    for (int j = 0; j < 8; j++) bb[j] = bias[tx * 8 + j];
    #pragma unroll
    for (int i = 0; i < 8; i++) {
        int row = bm + ty * 8 + i;
        if (row < N_NODES) {
            float4 o0, o1;
            o0.x = fmaxf(acc[i][0] + bb[0], 0.f);
            o0.y = fmaxf(acc[i][1] + bb[1], 0.f);
            o0.z = fmaxf(acc[i][2] + bb[2], 0.f);
            o0.w = fmaxf(acc[i][3] + bb[3], 0.f);
            o1.x = fmaxf(acc[i][4] + bb[4], 0.f);
            o1.y = fmaxf(acc[i][5] + bb[5], 0.f);
            o1.z = fmaxf(acc[i][6] + bb[6], 0.f);
            o1.w = fmaxf(acc[i][7] + bb[7], 0.f);
            *(float4*)&g_h1[(size_t)row * D + tx * 8] = o0;
            *(float4*)&g_h1[(size_t)row * D + tx * 8 + 4] = o1;
        }
    }
}

// ---------------- folded layer-2 + classifier: out = agg@W2lc + h1@W2rc + bcp
__global__ __launch_bounds__(256) void k_out(float* __restrict__ out) {
    __shared__ float sWl[D * NT];
    __shared__ float sWr[D * NT];
    __shared__ float sb[NT];
    for (int i = threadIdx.x; i < D * NT; i += 256) { sWl[i] = g_W2lc[i]; sWr[i] = g_W2rc[i]; }
    if (threadIdx.x < NT) sb[threadIdx.x] = g_bcp[threadIdx.x];
    __syncthreads();
    int warp = threadIdx.x >> 5, lane = threadIdx.x & 31;
    int node = blockIdx.x * 16 + warp * 2 + (lane >> 4);
    int c = lane & 15;
    if (node >= N_NODES) return;
    const float4* a4 = (const float4*)(g_agg + (size_t)node * D);
    const float4* h4 = (const float4*)(g_h1 + (size_t)node * D);
    float acc = sb[c];
    #pragma unroll 8
    for (int q = 0; q < 32; q++) {
        float4 av = a4[q], hv = h4[q];
        int k = q * 4;
        acc += av.x * sWl[(k + 0) * NT + c] + av.y * sWl[(k + 1) * NT + c]
             + av.z * sWl[(k + 2) * NT + c] + av.w * sWl[(k + 3) * NT + c];
        acc += hv.x * sWr[(k + 0) * NT + c] + hv.y * sWr[(k + 1) * NT + c]
             + hv.z * sWr[(k + 2) * NT + c] + hv.w * sWr[(k + 3) * NT + c];
    }
    out[node * NT + c] = acc;
}

// ---------------- launch ----------------
extern "C" void kernel_launch(void* const* d_in, const int* in_sizes, int n_in,
                              void* d_out, int out_size) {
    const int*   entity = (const int*)d_in[0];
    const int*   edge   = (const int*)d_in[1];
    const float* emb    = (const float*)d_in[2];
    const float* W1l    = (const float*)d_in[3];
    const float* b1     = (const float*)d_in[4];
    const float* W1r    = (const float*)d_in[5];
    const float* W2l    = (const float*)d_in[6];
    const float* b2     = (const float*)d_in[7];
    const float* W2r    = (const float*)d_in[8];
    const float* Wc     = (const float*)d_in[9];
    const float* bc     = (const float*)d_in[10];
    float* out = (float*)d_out;

    const int* src = edge;            // edge_index[0]
    const int* dst = edge + N_EDGES;  // edge_index[1]

    // CSR build (dst-keyed)
    k_zero_deg<<<(NCHUNK * CHUNK + 255) / 256, 256>>>();
    k_count<<<(N_EDGES + 255) / 256, 256>>>(dst);
    k_chunksum<<<NCHUNK, 256>>>();
    k_chunkoff<<<1, 32>>>();
    k_scan<<<NCHUNK, CHUNK>>>();
    k_fill<<<(N_EDGES + 255) / 256, 256>>>(src, dst);

    // feature pipeline
    k_gather<<<(N_NODES * 32 + 255) / 256, 256>>>(entity, emb);
    k_combine<<<2, 256>>>(W2l, W2r, b2, Wc, bc);

    k_agg<<<(N_NODES * 32 + 255) / 256, 256>>>(0);                 // agg = mean(x0)
    k_gemm<<<(N_NODES + 127) / 128, 256>>>(W1l, W1r, b1);          // h1
    k_agg<<<(N_NODES * 32 + 255) / 256, 256>>>(1);                 // agg = mean(h1)
    k_out<<<(N_NODES + 15) / 16, 256>>>(out);                      // final [N,16]
}

// round 2
// speedup vs baseline: 1.1497x; 1.1497x over previous
#include <cuda_runtime.h>
#include <cuda_bf16.h>

#define N_NODES 50000
#define N_EDGES 600000
#define D 128
#define NT 16
#define CHUNK 1024
#define NCHUNK 49   // ceil(50000/1024)

// ---------------- scratch (static __device__, no allocs) ----------------
__device__ float g_x0[N_NODES * D];     // embedded node features
__device__ float g_h1[N_NODES * D];     // layer-1 output
__device__ float g_agg[N_NODES * D];    // mean-aggregated neighbor features (layer 1)
__device__ float g_p[N_NODES * NT];     // h1 @ W2lc (projected before layer-2 agg)
__device__ int   g_deg[NCHUNK * CHUNK]; // padded degree array
__device__ int   g_off[N_NODES];        // CSR row offsets
__device__ int   g_cur[N_NODES];        // fill cursors
__device__ int   g_csr[N_EDGES];        // src lists grouped by dst
__device__ int   g_csum[NCHUNK];        // per-chunk sums -> offsets
__device__ float g_W2lc[D * NT];        // W2_l @ Wc (folded)
__device__ float g_W2rc[D * NT];        // W2_r @ Wc (folded)
__device__ float g_bcp[NT];             // b2 @ Wc + bc (folded)

// ---------------- CSR construction ----------------
__global__ void k_zero_deg() {
    int i = blockIdx.x * blockDim.x + threadIdx.x;
    if (i < NCHUNK * CHUNK) g_deg[i] = 0;
}

__global__ void k_count(const int* __restrict__ dst) {
    int e = blockIdx.x * blockDim.x + threadIdx.x;
    if (e < N_EDGES) atomicAdd(&g_deg[dst[e]], 1);
}

__global__ void k_chunksum() {
    __shared__ int s[256];
    int b = blockIdx.x, t = threadIdx.x;
    int base = b * CHUNK + t * 4;
    int v = g_deg[base] + g_deg[base + 1] + g_deg[base + 2] + g_deg[base + 3];
    s[t] = v;
    __syncthreads();
    for (int o = 128; o > 0; o >>= 1) {
        if (t < o) s[t] += s[t + o];
        __syncthreads();
    }
    if (t == 0) g_csum[b] = s[0];
}

// 64-thread shared-memory exclusive scan over NCHUNK entries
__global__ void k_chunkoff() {
    __shared__ int s[64];
    int t = threadIdx.x;
    int v = (t < NCHUNK) ? g_csum[t] : 0;
    s[t] = v;
    __syncthreads();
    #pragma unroll
    for (int o = 1; o < 64; o <<= 1) {
        int tmp = (t >= o) ? s[t - o] : 0;
        __syncthreads();
        s[t] += tmp;
        __syncthreads();
    }
    if (t < NCHUNK) g_csum[t] = s[t] - v;   // exclusive
}

__global__ void k_scan() {
    __shared__ int s[CHUNK];
    int b = blockIdx.x, t = threadIdx.x;
    int g = b * CHUNK + t;
    int v = g_deg[g];
    s[t] = v;
    __syncthreads();
    for (int o = 1; o < CHUNK; o <<= 1) {
        int tmp = (t >= o) ? s[t - o] : 0;
        __syncthreads();
        s[t] += tmp;
        __syncthreads();
    }
    if (g < N_NODES) {
        int excl = g_csum[b] + s[t] - v;
        g_off[g] = excl;
        g_cur[g] = excl;
    }
}

__global__ void k_fill(const int* __restrict__ src, const int* __restrict__ dst) {
    int e = blockIdx.x * blockDim.x + threadIdx.x;
    if (e < N_EDGES) {
        int p = atomicAdd(&g_cur[dst[e]], 1);
        g_csr[p] = src[e];
    }
}

// ---------------- embedding gather: x0 = emb[entity] ----------------
__global__ void k_gather(const int* __restrict__ entity, const float* __restrict__ emb) {
    int warp = (blockIdx.x * blockDim.x + threadIdx.x) >> 5;
    int lane = threadIdx.x & 31;
    if (warp >= N_NODES) return;
    int e = entity[warp];
    const float4* s = (const float4*)(emb + (size_t)e * D);
    float4* d = (float4*)(g_x0 + (size_t)warp * D);
    d[lane] = s[lane];
}

// ---------------- fold layer-2 weights through classifier ----------------
__global__ void k_combine(const float* __restrict__ W2l, const float* __restrict__ W2r,
                          const float* __restrict__ b2,  const float* __restrict__ Wc,
                          const float* __restrict__ bc) {
    __shared__ float sWc[D * NT];
    for (int i = threadIdx.x; i < D * NT; i += blockDim.x) sWc[i] = Wc[i];
    __syncthreads();
    const float* W = (blockIdx.x == 0) ? W2l : W2r;
    float* out = (blockIdx.x == 0) ? g_W2lc : g_W2rc;
    for (int o = threadIdx.x; o < D * NT; o += blockDim.x) {
        int i = o >> 4, c = o & 15;
        float acc = 0.f;
        #pragma unroll 8
        for (int k = 0; k < D; k++) acc += W[i * D + k] * sWc[k * NT + c];
        out[o] = acc;
    }
    if (blockIdx.x == 0 && threadIdx.x < NT) {
        int c = threadIdx.x;
        float acc = bc[c];
        for (int k = 0; k < D; k++) acc += b2[k] * sWc[k * NT + c];
        g_bcp[c] = acc;
    }
}

// ---------------- mean aggregation of x0 (layer 1): warp per node ----------------
__global__ __launch_bounds__(256) void k_agg() {
    const float* __restrict__ X = g_x0;
    int warp = (blockIdx.x * blockDim.x + threadIdx.x) >> 5;
    int lane = threadIdx.x & 31;
    if (warp >= N_NODES) return;
    int start = g_off[warp];
    int d = g_deg[warp];
    float ax = 0.f, ay = 0.f, az = 0.f, aw = 0.f;
    int e = 0;
    for (; e + 4 <= d; e += 4) {
        int s0 = g_csr[start + e + 0];
        int s1 = g_csr[start + e + 1];
        int s2 = g_csr[start + e + 2];
        int s3 = g_csr[start + e + 3];
        float4 v0 = ((const float4*)(X + (size_t)s0 * D))[lane];
        float4 v1 = ((const float4*)(X + (size_t)s1 * D))[lane];
        float4 v2 = ((const float4*)(X + (size_t)s2 * D))[lane];
        float4 v3 = ((const float4*)(X + (size_t)s3 * D))[lane];
        ax += v0.x + v1.x + v2.x + v3.x;
        ay += v0.y + v1.y + v2.y + v3.y;
        az += v0.z + v1.z + v2.z + v3.z;
        aw += v0.w + v1.w + v2.w + v3.w;
    }
    for (; e < d; e++) {
        int s0 = g_csr[start + e];
        float4 v0 = ((const float4*)(X + (size_t)s0 * D))[lane];
        ax += v0.x; ay += v0.y; az += v0.z; aw += v0.w;
    }
    float inv = 1.0f / (float)max(d, 1);
    float4 r = make_float4(ax * inv, ay * inv, az * inv, aw * inv);
    ((float4*)(g_agg + (size_t)warp * D))[lane] = r;
}

// ---------------- layer-1 fused GEMM with packed f32x2 FFMA ----------------
// h1 = relu(agg@W1l + x0@W1r + b1). 128x128 tile, K=256, 256 thr, 8x8/thread.
__device__ __forceinline__ unsigned long long ffma2(unsigned long long a,
                                                    unsigned long long b,
                                                    unsigned long long c) {
    unsigned long long d;
    asm("fma.rn.f32x2 %0, %1, %2, %3;" : "=l"(d) : "l"(a), "l"(b), "l"(c));
    return d;
}
__device__ __forceinline__ unsigned long long dup2(float x) {
    unsigned long long d;
    asm("mov.b64 %0, {%1, %1};" : "=l"(d) : "f"(x));
    return d;
}
__device__ __forceinline__ void unpk2(unsigned long long d, float& lo, float& hi) {
    asm("mov.b64 {%0, %1}, %2;" : "=f"(lo), "=f"(hi) : "l"(d));
}

__global__ __launch_bounds__(256) void k_gemm(const float* __restrict__ B1,
                                              const float* __restrict__ B2,
                                              const float* __restrict__ bias) {
    __shared__ float As[16][128];
    __shared__ float Bs[16][128];
    int bm = blockIdx.x * 128;
    int tid = threadIdx.x;
    int tx = tid & 15, ty = tid >> 4;
    unsigned long long acc2[8][4];  // 8 rows x 4 col-pairs (cols tx*8 .. tx*8+7)
    #pragma unroll
    for (int i = 0; i < 8; i++)
        #pragma unroll
        for (int j = 0; j < 4; j++) acc2[i][j] = 0ULL;

    for (int ch = 0; ch < 16; ch++) {
        const float* A = (ch < 8) ? g_agg : g_x0;
        const float* B = (ch < 8) ? B1 : B2;
        int k0 = (ch & 7) * 16;
        #pragma unroll
        for (int l = 0; l < 2; l++) {
            int idx = tid * 2 + l;          // 0..511
            int r = idx >> 2, c4 = idx & 3; // 128 rows x 4 float4
            int row = bm + r;
            float4 v = make_float4(0.f, 0.f, 0.f, 0.f);
            if (row < N_NODES) v = *(const float4*)(A + (size_t)row * D + k0 + c4 * 4);
            As[c4 * 4 + 0][r] = v.x;
            As[c4 * 4 + 1][r] = v.y;
            As[c4 * 4 + 2][r] = v.z;
            As[c4 * 4 + 3][r] = v.w;
        }
        #pragma unroll
        for (int l = 0; l < 2; l++) {
            int idx = tid * 2 + l;
            int r = idx >> 5, c4 = idx & 31; // 16 rows x 32 float4
            *(float4*)&Bs[r][c4 * 4] = *(const float4*)(B + (size_t)(k0 + r) * D + c4 * 4);
        }
        __syncthreads();
        #pragma unroll
        for (int k = 0; k < 16; k++) {
            float a[8];
            *(float4*)&a[0] = *(const float4*)&As[k][ty * 8];
            *(float4*)&a[4] = *(const float4*)&As[k][ty * 8 + 4];
            unsigned long long b2v[4];
            *(ulonglong2*)&b2v[0] = *(const ulonglong2*)&Bs[k][tx * 8];
            *(ulonglong2*)&b2v[2] = *(const ulonglong2*)&Bs[k][tx * 8 + 4];
            #pragma unroll
            for (int i = 0; i < 8; i++) {
                unsigned long long a2 = dup2(a[i]);
                #pragma unroll
                for (int j = 0; j < 4; j++)
                    acc2[i][j] = ffma2(a2, b2v[j], acc2[i][j]);
            }
        }
        __syncthreads();
    }

    float bb[8];
    #pragma unroll
    for (int j = 0; j < 8; j++) bb[j] = bias[tx * 8 + j];
    #pragma unroll
    for (int i = 0; i < 8; i++) {
        int row = bm + ty * 8 + i;
        if (row < N_NODES) {
            float c[8];
            #pragma unroll
            for (int j = 0; j < 4; j++) unpk2(acc2[i][j], c[2 * j], c[2 * j + 1]);
            float4 o0, o1;
            o0.x = fmaxf(c[0] + bb[0], 0.f);
            o0.y = fmaxf(c[1] + bb[1], 0.f);
            o0.z = fmaxf(c[2] + bb[2], 0.f);
            o0.w = fmaxf(c[3] + bb[3], 0.f);
            o1.x = fmaxf(c[4] + bb[4], 0.f);
            o1.y = fmaxf(c[5] + bb[5], 0.f);
            o1.z = fmaxf(c[6] + bb[6], 0.f);
            o1.w = fmaxf(c[7] + bb[7], 0.f);
            *(float4*)&g_h1[(size_t)row * D + tx * 8] = o0;
            *(float4*)&g_h1[(size_t)row * D + tx * 8 + 4] = o1;
        }
    }
}

// ---------------- p = h1 @ W2lc  [N,16] (project BEFORE layer-2 aggregation) ----
__global__ __launch_bounds__(256) void k_proj() {
    __shared__ float sWl[D * NT];
    for (int i = threadIdx.x; i < D * NT; i += 256) sWl[i] = g_W2lc[i];
    __syncthreads();
    int warp = threadIdx.x >> 5, lane = threadIdx.x & 31;
    int node = blockIdx.x * 16 + warp * 2 + (lane >> 4);
    int c = lane & 15;
    if (node >= N_NODES) return;
    const float4* h4 = (const float4*)(g_h1 + (size_t)node * D);
    float acc = 0.f;
    #pragma unroll 8
    for (int q = 0; q < 32; q++) {
        float4 hv = h4[q];
        int k = q * 4;
        acc += hv.x * sWl[(k + 0) * NT + c] + hv.y * sWl[(k + 1) * NT + c]
             + hv.z * sWl[(k + 2) * NT + c] + hv.w * sWl[(k + 3) * NT + c];
    }
    g_p[node * NT + c] = acc;
}

// ---------------- fused layer-2: out = mean_nbr(p) + h1@W2rc + bcp ----------------
__global__ __launch_bounds__(256) void k_out(float* __restrict__ out) {
    __shared__ float sWr[D * NT];
    __shared__ float sb[NT];
    for (int i = threadIdx.x; i < D * NT; i += 256) sWr[i] = g_W2rc[i];
    if (threadIdx.x < NT) sb[threadIdx.x] = g_bcp[threadIdx.x];
    __syncthreads();
    int warp = threadIdx.x >> 5, lane = threadIdx.x & 31;
    int node = blockIdx.x * 16 + warp * 2 + (lane >> 4);
    int c = lane & 15;
    if (node >= N_NODES) return;

    // self term: h1[node] @ W2rc[:,c]
    const float4* h4 = (const float4*)(g_h1 + (size_t)node * D);
    float acc = sb[c];
    #pragma unroll 8
    for (int q = 0; q < 32; q++) {
        float4 hv = h4[q];
        int k = q * 4;
        acc += hv.x * sWr[(k + 0) * NT + c] + hv.y * sWr[(k + 1) * NT + c]
             + hv.z * sWr[(k + 2) * NT + c] + hv.w * sWr[(k + 3) * NT + c];
    }

    // neighbor term: mean of p over in-neighbors (16 floats per edge)
    int start = g_off[node];
    int d = g_deg[node];
    float s = 0.f;
    int e = 0;
    for (; e + 4 <= d; e += 4) {
        int s0 = g_csr[start + e + 0];
        int s1 = g_csr[start + e + 1];
        int s2 = g_csr[start + e + 2];
        int s3 = g_csr[start + e + 3];
        s += g_p[s0 * NT + c] + g_p[s1 * NT + c] + g_p[s2 * NT + c] + g_p[s3 * NT + c];
    }
    for (; e < d; e++) s += g_p[g_csr[start + e] * NT + c];
    acc += s / (float)max(d, 1);

    out[node * NT + c] = acc;
}

// ---------------- launch ----------------
extern "C" void kernel_launch(void* const* d_in, const int* in_sizes, int n_in,
                              void* d_out, int out_size) {
    const int*   entity = (const int*)d_in[0];
    const int*   edge   = (const int*)d_in[1];
    const float* emb    = (const float*)d_in[2];
    const float* W1l    = (const float*)d_in[3];
    const float* b1     = (const float*)d_in[4];
    const float* W1r    = (const float*)d_in[5];
    const float* W2l    = (const float*)d_in[6];
    const float* b2     = (const float*)d_in[7];
    const float* W2r    = (const float*)d_in[8];
    const float* Wc     = (const float*)d_in[9];
    const float* bc     = (const float*)d_in[10];
    float* out = (float*)d_out;

    const int* src = edge;            // edge_index[0]
    const int* dst = edge + N_EDGES;  // edge_index[1]

    // CSR build (dst-keyed)
    k_zero_deg<<<(NCHUNK * CHUNK + 255) / 256, 256>>>();
    k_count<<<(N_EDGES + 255) / 256, 256>>>(dst);
    k_chunksum<<<NCHUNK, 256>>>();
    k_chunkoff<<<1, 64>>>();
    k_scan<<<NCHUNK, CHUNK>>>();
    k_fill<<<(N_EDGES + 255) / 256, 256>>>(src, dst);

    // feature pipeline
    k_gather<<<(N_NODES * 32 + 255) / 256, 256>>>(entity, emb);
    k_combine<<<2, 256>>>(W2l, W2r, b2, Wc, bc);

    k_agg<<<(N_NODES * 32 + 255) / 256, 256>>>();                  // agg = mean(x0)
    k_gemm<<<(N_NODES + 127) / 128, 256>>>(W1l, W1r, b1);          // h1 (FFMA2)
    k_proj<<<(N_NODES + 15) / 16, 256>>>();                        // p = h1@W2lc
    k_out<<<(N_NODES + 15) / 16, 256>>>(out);                      // out = mean(p)+h1@W2rc+bcp
}